// round 7
// baseline (speedup 1.0000x reference)
#include <cuda_runtime.h>
#include <cstdint>

#define HW      65536
#define NPIX    (16 * HW)
#define TPB     384
#define TILE_PX 128
#define NBLK    (NPIX / TILE_PX)   // 8192

typedef unsigned long long u64;

__device__ __forceinline__ u64 ffma2(u64 a, u64 b, u64 c) {
    u64 d;
    asm("fma.rn.f32x2 %0, %1, %2, %3;" : "=l"(d) : "l"(a), "l"(b), "l"(c));
    return d;
}
__device__ __forceinline__ u64 pack2(float lo, float hi) {
    u64 d;
    asm("mov.b64 %0, {%1, %2};" : "=l"(d) : "f"(lo), "f"(hi));
    return d;
}
__device__ __forceinline__ void unpack2(u64 v, float& lo, float& hi) {
    asm("mov.b64 {%0, %1}, %2;" : "=f"(lo), "=f"(hi) : "l"(v));
}

// ---- dynamic smem layout (float units, all u64 arrays at even offsets) ----
#define F_SW2   0                        // u64 [64][96] dup conv weights  (12288 f)
#define F_SOUT  12288                    // f32 [96][128] conv outputs     (12288 f)
#define F_BIASD 24576                    // u64 [96] dup k|v|q bias        (192 f)
#define F_SD1P  24768                    // u64 [32][8] d1 out-pairs       (512 f)
#define F_SD2P  25280                    // u64 [16][4]                    (128 f)
#define F_SD3P  25408                    // u64 [8][8]                     (128 f)
#define F_SB3   25536                    // f32 [16]
#define F_SSCL  25552                    // f32 [1]
#define F_TOTAL 25556
#define SMEM_BYTES (F_TOTAL * 4)         // 102,224 B -> 2 CTAs/SM

__global__ void __launch_bounds__(TPB, 2)
fused_px2_kernel(
    const float* __restrict__ kv_in, const float* __restrict__ q_in,
    const float* __restrict__ key_w, const float* __restrict__ key_b,
    const float* __restrict__ value_w, const float* __restrict__ value_b,
    const float* __restrict__ query_w, const float* __restrict__ query_b,
    const float* __restrict__ scale_p,
    const float* __restrict__ d1_w, const float* __restrict__ d2_w,
    const float* __restrict__ d3_w, const float* __restrict__ d3_b,
    float* __restrict__ out)
{
    extern __shared__ __align__(16) float sm[];
    u64*   sW2   = reinterpret_cast<u64*>(sm + F_SW2);     // [c*96 + o] = {w,w}
    float* sOut  = sm + F_SOUT;                            // [o*128 + px]
    u64*   sBd   = reinterpret_cast<u64*>(sm + F_BIASD);
    u64*   sD1p  = reinterpret_cast<u64*>(sm + F_SD1P);
    u64*   sD2p  = reinterpret_cast<u64*>(sm + F_SD2P);
    u64*   sD3p  = reinterpret_cast<u64*>(sm + F_SD3P);
    float* sB3   = sm + F_SB3;
    float* sScl  = sm + F_SSCL;

    const int tid  = threadIdx.x;
    const int wid  = tid >> 5;     // 0..11
    const int lane = tid & 31;
    const int px0  = lane * 4;

    // ---- stage weights ----
    for (int i = tid; i < 96 * 64; i += TPB) {
        int o = i >> 6, c = i & 63;
        float w = (o < 32) ? key_w[o * 64 + c]
                : (o < 64) ? value_w[(o - 32) * 64 + c]
                           : query_w[(o - 64) * 64 + c];
        sW2[c * 96 + o] = pack2(w, w);
    }
    if (tid < 96) {
        float bv = (tid < 32) ? key_b[tid] : (tid < 64) ? value_b[tid - 32]
                                                        : query_b[tid - 64];
        sBd[tid] = pack2(bv, bv);
    }
    for (int i = tid; i < 32 * 8; i += TPB) {      // d1 pairs
        int c = i >> 3, j = i & 7;
        sD1p[c * 8 + j] = pack2(d1_w[(2 * j) * 32 + c], d1_w[(2 * j + 1) * 32 + c]);
    }
    if (tid < 64) {                                 // d2 pairs: [16][4]
        int c = tid >> 2, j = tid & 3;
        sD2p[c * 4 + j] = pack2(d2_w[(2 * j) * 16 + c], d2_w[(2 * j + 1) * 16 + c]);
    }
    if (tid >= 64 && tid < 128) {                   // d3 pairs: [8][8]
        int i = tid - 64;
        int c = i >> 3, j = i & 7;
        sD3p[c * 8 + j] = pack2(d3_w[(2 * j) * 8 + c], d3_w[(2 * j + 1) * 8 + c]);
    }
    if (tid < 16) sB3[tid] = d3_b[tid];
    if (tid == 0) sScl[0] = scale_p[0];
    __syncthreads();

    const int p0   = blockIdx.x * TILE_PX;
    const int b    = p0 >> 16;
    const int poff = p0 & (HW - 1);

    // ---- conv: warp w -> 8 outs; thread: 4 px (2 pairs) x 8 outs ----
    const int obase = (wid < 8) ? wid * 8 : 64 + (wid - 8) * 8;
    const float* src = ((wid < 8) ? kv_in : q_in)
                     + (size_t)b * 64 * HW + poff + px0;

    u64 acc0[8], acc1[8];      // acc0 = px(0,1), acc1 = px(2,3)
    #pragma unroll
    for (int j = 0; j < 8; ++j) {
        u64 bj = sBd[obase + j];
        acc0[j] = bj;
        acc1[j] = bj;
    }

    const u64* wbase = sW2 + obase;
    #pragma unroll 2
    for (int c = 0; c < 64; ++c) {
        float4 a = __ldg(reinterpret_cast<const float4*>(src + (size_t)c * HW));
        u64 a01 = pack2(a.x, a.y);
        u64 a23 = pack2(a.z, a.w);
        const ulonglong2* wp = reinterpret_cast<const ulonglong2*>(wbase + c * 96);
        #pragma unroll
        for (int j = 0; j < 4; ++j) {
            ulonglong2 w = wp[j];
            acc0[2 * j]     = ffma2(a01, w.x, acc0[2 * j]);
            acc1[2 * j]     = ffma2(a23, w.x, acc1[2 * j]);
            acc0[2 * j + 1] = ffma2(a01, w.y, acc0[2 * j + 1]);
            acc1[2 * j + 1] = ffma2(a23, w.y, acc1[2 * j + 1]);
        }
    }

    // ---- redistribute: one STS.128 per out (4 px contiguous) ----
    #pragma unroll
    for (int j = 0; j < 8; ++j) {
        ulonglong2 v;
        v.x = acc0[j];
        v.y = acc1[j];
        *reinterpret_cast<ulonglong2*>(&sOut[(obase + j) * TILE_PX + px0]) = v;
    }
    __syncthreads();

    // ---- epilogue: threads 0..127, one pixel each ----
    if (tid < TILE_PX) {
        const int px = tid;
        const float scl = sScl[0];

        float x[32];
        #pragma unroll
        for (int o = 0; o < 32; ++o) {
            float kk = sOut[o * TILE_PX + px];
            float vv = sOut[(32 + o) * TILE_PX + px];
            float qq = sOut[(64 + o) * TILE_PX + px];
            float z = kk * qq * scl;
            float g = __fdividef(1.0f, 1.0f + __expf(-z));
            x[o] = g * vv;
        }

        // d1: 32 -> 16 (packed out-pairs), relu
        u64 h1p[8];
        #pragma unroll
        for (int j = 0; j < 8; ++j) h1p[j] = 0ull;
        #pragma unroll
        for (int c = 0; c < 32; ++c) {
            u64 xx = pack2(x[c], x[c]);
            const ulonglong2* wr = reinterpret_cast<const ulonglong2*>(&sD1p[c * 8]);
            #pragma unroll
            for (int j = 0; j < 4; ++j) {
                ulonglong2 w = wr[j];
                h1p[2 * j]     = ffma2(xx, w.x, h1p[2 * j]);
                h1p[2 * j + 1] = ffma2(xx, w.y, h1p[2 * j + 1]);
            }
        }
        float h1[16];
        #pragma unroll
        for (int j = 0; j < 8; ++j) {
            float lo, hi; unpack2(h1p[j], lo, hi);
            h1[2 * j]     = fmaxf(lo, 0.0f);
            h1[2 * j + 1] = fmaxf(hi, 0.0f);
        }

        // d2: 16 -> 8, relu
        u64 h2p[4];
        #pragma unroll
        for (int j = 0; j < 4; ++j) h2p[j] = 0ull;
        #pragma unroll
        for (int c = 0; c < 16; ++c) {
            u64 xx = pack2(h1[c], h1[c]);
            const ulonglong2* wr = reinterpret_cast<const ulonglong2*>(&sD2p[c * 4]);
            #pragma unroll
            for (int j = 0; j < 2; ++j) {
                ulonglong2 w = wr[j];
                h2p[2 * j]     = ffma2(xx, w.x, h2p[2 * j]);
                h2p[2 * j + 1] = ffma2(xx, w.y, h2p[2 * j + 1]);
            }
        }
        float h2[8];
        #pragma unroll
        for (int j = 0; j < 4; ++j) {
            float lo, hi; unpack2(h2p[j], lo, hi);
            h2[2 * j]     = fmaxf(lo, 0.0f);
            h2[2 * j + 1] = fmaxf(hi, 0.0f);
        }

        // d3: 8 -> 16 + bias
        u64 o16p[8];
        {
            const u64* b3p = reinterpret_cast<const u64*>(sB3);
            #pragma unroll
            for (int j = 0; j < 8; ++j) o16p[j] = b3p[j];
        }
        #pragma unroll
        for (int c = 0; c < 8; ++c) {
            u64 xx = pack2(h2[c], h2[c]);
            const ulonglong2* wr = reinterpret_cast<const ulonglong2*>(&sD3p[c * 8]);
            #pragma unroll
            for (int j = 0; j < 4; ++j) {
                ulonglong2 w = wr[j];
                o16p[2 * j]     = ffma2(xx, w.x, o16p[2 * j]);
                o16p[2 * j + 1] = ffma2(xx, w.y, o16p[2 * j + 1]);
            }
        }

        float* op = out + ((size_t)b * 16) * HW + poff + px;
        #pragma unroll
        for (int j = 0; j < 8; ++j) {
            float lo, hi; unpack2(o16p[j], lo, hi);
            op[(size_t)(2 * j) * HW]     = lo;
            op[(size_t)(2 * j + 1) * HW] = hi;
        }
    }
}

extern "C" void kernel_launch(void* const* d_in, const int* in_sizes, int n_in,
                              void* d_out, int out_size)
{
    cudaFuncSetAttribute(fused_px2_kernel,
                         cudaFuncAttributeMaxDynamicSharedMemorySize, SMEM_BYTES);
    fused_px2_kernel<<<NBLK, TPB, SMEM_BYTES>>>(
        (const float*)d_in[0], (const float*)d_in[1],
        (const float*)d_in[2], (const float*)d_in[3],
        (const float*)d_in[4], (const float*)d_in[5],
        (const float*)d_in[6], (const float*)d_in[7],
        (const float*)d_in[8],
        (const float*)d_in[9], (const float*)d_in[10],
        (const float*)d_in[11], (const float*)d_in[12],
        (float*)d_out);
}

// round 8
// speedup vs baseline: 1.3570x; 1.3570x over previous
#include <cuda_runtime.h>
#include <cstdint>

#define HW      65536
#define NPIX    (16 * HW)
#define TPB     384
#define TILE_PX 128
#define NBLK    (NPIX / TILE_PX)   // 8192

typedef unsigned long long u64;

__device__ __forceinline__ u64 ffma2(u64 a, u64 b, u64 c) {
    u64 d;
    asm("fma.rn.f32x2 %0, %1, %2, %3;" : "=l"(d) : "l"(a), "l"(b), "l"(c));
    return d;
}
__device__ __forceinline__ u64 pack2(float lo, float hi) {
    u64 d;
    asm("mov.b64 %0, {%1, %2};" : "=l"(d) : "f"(lo), "f"(hi));
    return d;
}
__device__ __forceinline__ void unpack2(u64 v, float& lo, float& hi) {
    asm("mov.b64 {%0, %1}, %2;" : "=f"(lo), "=f"(hi) : "l"(v));
}

// ---- dynamic smem layout (float units) ----
#define F_SW2   0                        // u64 [64][96] dup conv weights
#define F_SOUT  12288                    // f32 [96][128] conv outputs
#define F_BIASD 24576                    // u64 [96] dup bias
#define F_SD1P  24768                    // u64 [32][8]
#define F_SD2P  25280                    // u64 [16][4]
#define F_SD3P  25408                    // u64 [8][8]
#define F_SB3   25536                    // f32 [16]
#define F_SSCL  25552
#define F_TOTAL 25556
#define SMEM_BYTES (F_TOTAL * 4)         // 102,224 B -> 2 CTAs/SM

__global__ void __launch_bounds__(TPB, 2)
fused_px2_kernel(
    const float* __restrict__ kv_in, const float* __restrict__ q_in,
    const float* __restrict__ key_w, const float* __restrict__ key_b,
    const float* __restrict__ value_w, const float* __restrict__ value_b,
    const float* __restrict__ query_w, const float* __restrict__ query_b,
    const float* __restrict__ scale_p,
    const float* __restrict__ d1_w, const float* __restrict__ d2_w,
    const float* __restrict__ d3_w, const float* __restrict__ d3_b,
    float* __restrict__ out)
{
    extern __shared__ __align__(16) float sm[];
    u64*   sW2   = reinterpret_cast<u64*>(sm + F_SW2);
    float* sOut  = sm + F_SOUT;
    u64*   sBd   = reinterpret_cast<u64*>(sm + F_BIASD);
    u64*   sD1p  = reinterpret_cast<u64*>(sm + F_SD1P);
    u64*   sD2p  = reinterpret_cast<u64*>(sm + F_SD2P);
    u64*   sD3p  = reinterpret_cast<u64*>(sm + F_SD3P);
    float* sB3   = sm + F_SB3;
    float* sScl  = sm + F_SSCL;

    const int tid  = threadIdx.x;
    const int wid  = tid >> 5;
    const int lane = tid & 31;
    const int px0  = lane * 4;

    // ---- stage weights ----
    for (int i = tid; i < 96 * 64; i += TPB) {
        int o = i >> 6, c = i & 63;
        float w = (o < 32) ? key_w[o * 64 + c]
                : (o < 64) ? value_w[(o - 32) * 64 + c]
                           : query_w[(o - 64) * 64 + c];
        sW2[c * 96 + o] = pack2(w, w);
    }
    if (tid < 96) {
        float bv = (tid < 32) ? key_b[tid] : (tid < 64) ? value_b[tid - 32]
                                                        : query_b[tid - 64];
        sBd[tid] = pack2(bv, bv);
    }
    for (int i = tid; i < 32 * 8; i += TPB) {
        int c = i >> 3, j = i & 7;
        sD1p[c * 8 + j] = pack2(d1_w[(2 * j) * 32 + c], d1_w[(2 * j + 1) * 32 + c]);
    }
    if (tid < 64) {
        int c = tid >> 2, j = tid & 3;
        sD2p[c * 4 + j] = pack2(d2_w[(2 * j) * 16 + c], d2_w[(2 * j + 1) * 16 + c]);
    }
    if (tid >= 64 && tid < 128) {
        int i = tid - 64;
        int c = i >> 3, j = i & 7;
        sD3p[c * 8 + j] = pack2(d3_w[(2 * j) * 8 + c], d3_w[(2 * j + 1) * 8 + c]);
    }
    if (tid < 16) sB3[tid] = d3_b[tid];
    if (tid == 0) sScl[0] = scale_p[0];
    __syncthreads();

    const int p0   = blockIdx.x * TILE_PX;
    const int b    = p0 >> 16;
    const int poff = p0 & (HW - 1);

    const int obase = (wid < 8) ? wid * 8 : 64 + (wid - 8) * 8;
    const float* src = ((wid < 8) ? kv_in : q_in)
                     + (size_t)b * 64 * HW + poff + px0;

    u64 acc0[8], acc1[8];
    #pragma unroll
    for (int j = 0; j < 8; ++j) {
        u64 bj = sBd[obase + j];
        acc0[j] = bj;
        acc1[j] = bj;
    }

    const u64* wbase = sW2 + obase;
    // deep unroll -> 8 batched LDG.128 (MLP ~8) to hide L2/DRAM latency
    #pragma unroll 8
    for (int c = 0; c < 64; ++c) {
        float4 a = __ldg(reinterpret_cast<const float4*>(src + (size_t)c * HW));
        u64 a01 = pack2(a.x, a.y);
        u64 a23 = pack2(a.z, a.w);
        const ulonglong2* wp = reinterpret_cast<const ulonglong2*>(wbase + c * 96);
        #pragma unroll
        for (int j = 0; j < 4; ++j) {
            ulonglong2 w = wp[j];
            acc0[2 * j]     = ffma2(a01, w.x, acc0[2 * j]);
            acc1[2 * j]     = ffma2(a23, w.x, acc1[2 * j]);
            acc0[2 * j + 1] = ffma2(a01, w.y, acc0[2 * j + 1]);
            acc1[2 * j + 1] = ffma2(a23, w.y, acc1[2 * j + 1]);
        }
    }

    // ---- redistribute: one STS.128 per out ----
    #pragma unroll
    for (int j = 0; j < 8; ++j) {
        ulonglong2 v;
        v.x = acc0[j];
        v.y = acc1[j];
        *reinterpret_cast<ulonglong2*>(&sOut[(obase + j) * TILE_PX + px0]) = v;
    }
    __syncthreads();

    // ---- epilogue: threads 0..127, one pixel each ----
    if (tid < TILE_PX) {
        const int px = tid;
        const float scl = sScl[0];

        float x[32];
        #pragma unroll
        for (int o = 0; o < 32; ++o) {
            float kk = sOut[o * TILE_PX + px];
            float vv = sOut[(32 + o) * TILE_PX + px];
            float qq = sOut[(64 + o) * TILE_PX + px];
            float z = kk * qq * scl;
            float g = __fdividef(1.0f, 1.0f + __expf(-z));
            x[o] = g * vv;
        }

        u64 h1p[8];
        #pragma unroll
        for (int j = 0; j < 8; ++j) h1p[j] = 0ull;
        #pragma unroll
        for (int c = 0; c < 32; ++c) {
            u64 xx = pack2(x[c], x[c]);
            const ulonglong2* wr = reinterpret_cast<const ulonglong2*>(&sD1p[c * 8]);
            #pragma unroll
            for (int j = 0; j < 4; ++j) {
                ulonglong2 w = wr[j];
                h1p[2 * j]     = ffma2(xx, w.x, h1p[2 * j]);
                h1p[2 * j + 1] = ffma2(xx, w.y, h1p[2 * j + 1]);
            }
        }
        float h1[16];
        #pragma unroll
        for (int j = 0; j < 8; ++j) {
            float lo, hi; unpack2(h1p[j], lo, hi);
            h1[2 * j]     = fmaxf(lo, 0.0f);
            h1[2 * j + 1] = fmaxf(hi, 0.0f);
        }

        u64 h2p[4];
        #pragma unroll
        for (int j = 0; j < 4; ++j) h2p[j] = 0ull;
        #pragma unroll
        for (int c = 0; c < 16; ++c) {
            u64 xx = pack2(h1[c], h1[c]);
            const ulonglong2* wr = reinterpret_cast<const ulonglong2*>(&sD2p[c * 4]);
            #pragma unroll
            for (int j = 0; j < 2; ++j) {
                ulonglong2 w = wr[j];
                h2p[2 * j]     = ffma2(xx, w.x, h2p[2 * j]);
                h2p[2 * j + 1] = ffma2(xx, w.y, h2p[2 * j + 1]);
            }
        }
        float h2[8];
        #pragma unroll
        for (int j = 0; j < 4; ++j) {
            float lo, hi; unpack2(h2p[j], lo, hi);
            h2[2 * j]     = fmaxf(lo, 0.0f);
            h2[2 * j + 1] = fmaxf(hi, 0.0f);
        }

        u64 o16p[8];
        {
            const u64* b3p = reinterpret_cast<const u64*>(sB3);
            #pragma unroll
            for (int j = 0; j < 8; ++j) o16p[j] = b3p[j];
        }
        #pragma unroll
        for (int c = 0; c < 8; ++c) {
            u64 xx = pack2(h2[c], h2[c]);
            const ulonglong2* wr = reinterpret_cast<const ulonglong2*>(&sD3p[c * 8]);
            #pragma unroll
            for (int j = 0; j < 4; ++j) {
                ulonglong2 w = wr[j];
                o16p[2 * j]     = ffma2(xx, w.x, o16p[2 * j]);
                o16p[2 * j + 1] = ffma2(xx, w.y, o16p[2 * j + 1]);
            }
        }

        float* op = out + ((size_t)b * 16) * HW + poff + px;
        #pragma unroll
        for (int j = 0; j < 8; ++j) {
            float lo, hi; unpack2(o16p[j], lo, hi);
            op[(size_t)(2 * j) * HW]     = lo;
            op[(size_t)(2 * j + 1) * HW] = hi;
        }
    }
}

extern "C" void kernel_launch(void* const* d_in, const int* in_sizes, int n_in,
                              void* d_out, int out_size)
{
    cudaFuncSetAttribute(fused_px2_kernel,
                         cudaFuncAttributeMaxDynamicSharedMemorySize, SMEM_BYTES);
    fused_px2_kernel<<<NBLK, TPB, SMEM_BYTES>>>(
        (const float*)d_in[0], (const float*)d_in[1],
        (const float*)d_in[2], (const float*)d_in[3],
        (const float*)d_in[4], (const float*)d_in[5],
        (const float*)d_in[6], (const float*)d_in[7],
        (const float*)d_in[8],
        (const float*)d_in[9], (const float*)d_in[10],
        (const float*)d_in[11], (const float*)d_in[12],
        (float*)d_out);
}

// round 9
// speedup vs baseline: 1.6362x; 1.2057x over previous
#include <cuda_runtime.h>
#include <cstdint>

#define HW      65536
#define NPIX    (16 * HW)
#define TPB     192
#define TILE_PX 128
#define NBLK    (NPIX / TILE_PX)   // 8192
#define PITCH   100                // sOut row pitch in floats (conflict-free)

typedef unsigned long long u64;

__device__ __forceinline__ u64 ffma2(u64 a, u64 b, u64 c) {
    u64 d;
    asm("fma.rn.f32x2 %0, %1, %2, %3;" : "=l"(d) : "l"(a), "l"(b), "l"(c));
    return d;
}
__device__ __forceinline__ u64 pack2(float lo, float hi) {
    u64 d;
    asm("mov.b64 %0, {%1, %2};" : "=l"(d) : "f"(lo), "f"(hi));
    return d;
}
__device__ __forceinline__ void unpack2(u64 v, float& lo, float& hi) {
    asm("mov.b64 {%0, %1}, %2;" : "=f"(lo), "=f"(hi) : "l"(v));
}

// ---- dynamic smem layout (float units; u64 arrays even-aligned) ----
#define F_SWP   0                          // u64 [64][48] out-pair conv weights (6144 f)
#define F_SOUT  6144                       // f32 [128][PITCH]                  (12800 f)
#define F_SBP   18944                      // u64 [48] out-pair conv bias       (96 f)
#define F_SD1P  19040                      // u64 [32][8]                       (512 f)
#define F_SD2P  19552                      // u64 [16][4]                       (128 f)
#define F_SD3P  19680                      // u64 [8][8]                        (128 f)
#define F_SB3   19808                      // f32 [16]
#define F_SSCL  19824
#define F_TOTAL 19828
#define SMEM_BYTES (F_TOTAL * 4)           // 79,312 B -> 2 CTAs/SM

__global__ void __launch_bounds__(TPB, 2)
fused_o16_kernel(
    const float* __restrict__ kv_in, const float* __restrict__ q_in,
    const float* __restrict__ key_w, const float* __restrict__ key_b,
    const float* __restrict__ value_w, const float* __restrict__ value_b,
    const float* __restrict__ query_w, const float* __restrict__ query_b,
    const float* __restrict__ scale_p,
    const float* __restrict__ d1_w, const float* __restrict__ d2_w,
    const float* __restrict__ d3_w, const float* __restrict__ d3_b,
    float* __restrict__ out)
{
    extern __shared__ __align__(16) float sm[];
    u64*   sWp  = reinterpret_cast<u64*>(sm + F_SWP);   // [c*48 + pair]
    float* sOut = sm + F_SOUT;                          // [px*PITCH + out]
    u64*   sBp  = reinterpret_cast<u64*>(sm + F_SBP);
    u64*   sD1p = reinterpret_cast<u64*>(sm + F_SD1P);
    u64*   sD2p = reinterpret_cast<u64*>(sm + F_SD2P);
    u64*   sD3p = reinterpret_cast<u64*>(sm + F_SD3P);
    float* sB3  = sm + F_SB3;
    float* sScl = sm + F_SSCL;

    const int tid  = threadIdx.x;
    const int wid  = tid >> 5;     // 0..5
    const int lane = tid & 31;
    const int px0  = lane * 4;

    // ---- stage conv weights as out-pairs {w_2p, w_2p+1} ----
    for (int i = tid; i < 64 * 48; i += TPB) {
        int c = i / 48, p = i % 48;
        int o0 = 2 * p, o1 = 2 * p + 1;
        float w0 = (o0 < 32) ? key_w[o0 * 64 + c]
                 : (o0 < 64) ? value_w[(o0 - 32) * 64 + c]
                             : query_w[(o0 - 64) * 64 + c];
        float w1 = (o1 < 32) ? key_w[o1 * 64 + c]
                 : (o1 < 64) ? value_w[(o1 - 32) * 64 + c]
                             : query_w[(o1 - 64) * 64 + c];
        sWp[c * 48 + p] = pack2(w0, w1);
    }
    if (tid < 48) {
        int o0 = 2 * tid, o1 = o0 + 1;
        float b0 = (o0 < 32) ? key_b[o0] : (o0 < 64) ? value_b[o0 - 32] : query_b[o0 - 64];
        float b1 = (o1 < 32) ? key_b[o1] : (o1 < 64) ? value_b[o1 - 32] : query_b[o1 - 64];
        sBp[tid] = pack2(b0, b1);
    }
    for (int i = tid; i < 32 * 8; i += TPB) {
        int c = i >> 3, j = i & 7;
        sD1p[c * 8 + j] = pack2(d1_w[(2 * j) * 32 + c], d1_w[(2 * j + 1) * 32 + c]);
    }
    if (tid < 64) {
        int c = tid >> 2, j = tid & 3;
        sD2p[c * 4 + j] = pack2(d2_w[(2 * j) * 16 + c], d2_w[(2 * j + 1) * 16 + c]);
    }
    if (tid >= 64 && tid < 128) {
        int i = tid - 64;
        int c = i >> 3, j = i & 7;
        sD3p[c * 8 + j] = pack2(d3_w[(2 * j) * 8 + c], d3_w[(2 * j + 1) * 8 + c]);
    }
    if (tid < 16) sB3[tid] = d3_b[tid];
    if (tid == 0) sScl[0] = scale_p[0];
    __syncthreads();

    const int p0   = blockIdx.x * TILE_PX;
    const int b    = p0 >> 16;
    const int poff = p0 & (HW - 1);

    // ---- conv: warp w -> 16 outs (8 pairs); thread: 4 px x 8 out-pairs ----
    const int pbase = (wid < 4) ? wid * 8 : 32 + (wid - 4) * 8;   // pair base
    const float* src = ((wid < 4) ? kv_in : q_in)
                     + (size_t)b * 64 * HW + poff + px0;

    u64 acc[4][8];   // [px][out-pair]
    #pragma unroll
    for (int j = 0; j < 8; ++j) {
        u64 bj = sBp[pbase + j];
        acc[0][j] = bj; acc[1][j] = bj; acc[2][j] = bj; acc[3][j] = bj;
    }

    const u64* wb = sWp + pbase;
    #pragma unroll 8
    for (int c = 0; c < 64; ++c) {
        float4 a = __ldg(reinterpret_cast<const float4*>(src + (size_t)c * HW));
        u64 a0 = pack2(a.x, a.x);
        u64 a1 = pack2(a.y, a.y);
        u64 a2 = pack2(a.z, a.z);
        u64 a3 = pack2(a.w, a.w);
        const ulonglong2* wp = reinterpret_cast<const ulonglong2*>(wb + c * 48);
        #pragma unroll
        for (int j = 0; j < 4; ++j) {
            ulonglong2 w = wp[j];
            acc[0][2*j]   = ffma2(a0, w.x, acc[0][2*j]);
            acc[1][2*j]   = ffma2(a1, w.x, acc[1][2*j]);
            acc[2][2*j]   = ffma2(a2, w.x, acc[2][2*j]);
            acc[3][2*j]   = ffma2(a3, w.x, acc[3][2*j]);
            acc[0][2*j+1] = ffma2(a0, w.y, acc[0][2*j+1]);
            acc[1][2*j+1] = ffma2(a1, w.y, acc[1][2*j+1]);
            acc[2][2*j+1] = ffma2(a2, w.y, acc[2][2*j+1]);
            acc[3][2*j+1] = ffma2(a3, w.y, acc[3][2*j+1]);
        }
    }

    // ---- redistribute: sOut[px][out], 4 STS.128 per px ----
    #pragma unroll
    for (int px = 0; px < 4; ++px) {
        u64* row = reinterpret_cast<u64*>(sOut + (px0 + px) * PITCH) + pbase;
        ulonglong2* r2 = reinterpret_cast<ulonglong2*>(row);
        #pragma unroll
        for (int j = 0; j < 4; ++j) {
            ulonglong2 v;
            v.x = acc[px][2*j];
            v.y = acc[px][2*j+1];
            r2[j] = v;
        }
    }
    __syncthreads();

    // ---- epilogue: threads 0..127, one pixel each ----
    if (tid < TILE_PX) {
        const int px = tid;
        const float scl = sScl[0];
        const float* row = sOut + px * PITCH;

        float x[32];
        #pragma unroll
        for (int o = 0; o < 32; o += 4) {
            float4 kk = *reinterpret_cast<const float4*>(row + o);
            float4 vv = *reinterpret_cast<const float4*>(row + 32 + o);
            float4 qq = *reinterpret_cast<const float4*>(row + 64 + o);
            float z0 = kk.x * qq.x * scl;
            float z1 = kk.y * qq.y * scl;
            float z2 = kk.z * qq.z * scl;
            float z3 = kk.w * qq.w * scl;
            x[o+0] = vv.x * __fdividef(1.0f, 1.0f + __expf(-z0));
            x[o+1] = vv.y * __fdividef(1.0f, 1.0f + __expf(-z1));
            x[o+2] = vv.z * __fdividef(1.0f, 1.0f + __expf(-z2));
            x[o+3] = vv.w * __fdividef(1.0f, 1.0f + __expf(-z3));
        }

        u64 h1p[8];
        #pragma unroll
        for (int j = 0; j < 8; ++j) h1p[j] = 0ull;
        #pragma unroll
        for (int c = 0; c < 32; ++c) {
            u64 xx = pack2(x[c], x[c]);
            const ulonglong2* wr = reinterpret_cast<const ulonglong2*>(&sD1p[c * 8]);
            #pragma unroll
            for (int j = 0; j < 4; ++j) {
                ulonglong2 w = wr[j];
                h1p[2*j]   = ffma2(xx, w.x, h1p[2*j]);
                h1p[2*j+1] = ffma2(xx, w.y, h1p[2*j+1]);
            }
        }
        float h1[16];
        #pragma unroll
        for (int j = 0; j < 8; ++j) {
            float lo, hi; unpack2(h1p[j], lo, hi);
            h1[2*j]   = fmaxf(lo, 0.0f);
            h1[2*j+1] = fmaxf(hi, 0.0f);
        }

        u64 h2p[4];
        #pragma unroll
        for (int j = 0; j < 4; ++j) h2p[j] = 0ull;
        #pragma unroll
        for (int c = 0; c < 16; ++c) {
            u64 xx = pack2(h1[c], h1[c]);
            const ulonglong2* wr = reinterpret_cast<const ulonglong2*>(&sD2p[c * 4]);
            #pragma unroll
            for (int j = 0; j < 2; ++j) {
                ulonglong2 w = wr[j];
                h2p[2*j]   = ffma2(xx, w.x, h2p[2*j]);
                h2p[2*j+1] = ffma2(xx, w.y, h2p[2*j+1]);
            }
        }
        float h2[8];
        #pragma unroll
        for (int j = 0; j < 4; ++j) {
            float lo, hi; unpack2(h2p[j], lo, hi);
            h2[2*j]   = fmaxf(lo, 0.0f);
            h2[2*j+1] = fmaxf(hi, 0.0f);
        }

        u64 o16p[8];
        {
            const u64* b3p = reinterpret_cast<const u64*>(sB3);
            #pragma unroll
            for (int j = 0; j < 8; ++j) o16p[j] = b3p[j];
        }
        #pragma unroll
        for (int c = 0; c < 8; ++c) {
            u64 xx = pack2(h2[c], h2[c]);
            const ulonglong2* wr = reinterpret_cast<const ulonglong2*>(&sD3p[c * 8]);
            #pragma unroll
            for (int j = 0; j < 4; ++j) {
                ulonglong2 w = wr[j];
                o16p[2*j]   = ffma2(xx, w.x, o16p[2*j]);
                o16p[2*j+1] = ffma2(xx, w.y, o16p[2*j+1]);
            }
        }

        float* op = out + ((size_t)b * 16) * HW + poff + px;
        #pragma unroll
        for (int j = 0; j < 8; ++j) {
            float lo, hi; unpack2(o16p[j], lo, hi);
            op[(size_t)(2*j) * HW]     = lo;
            op[(size_t)(2*j+1) * HW]   = hi;
        }
    }
}

extern "C" void kernel_launch(void* const* d_in, const int* in_sizes, int n_in,
                              void* d_out, int out_size)
{
    cudaFuncSetAttribute(fused_o16_kernel,
                         cudaFuncAttributeMaxDynamicSharedMemorySize, SMEM_BYTES);
    fused_o16_kernel<<<NBLK, TPB, SMEM_BYTES>>>(
        (const float*)d_in[0], (const float*)d_in[1],
        (const float*)d_in[2], (const float*)d_in[3],
        (const float*)d_in[4], (const float*)d_in[5],
        (const float*)d_in[6], (const float*)d_in[7],
        (const float*)d_in[8],
        (const float*)d_in[9], (const float*)d_in[10],
        (const float*)d_in[11], (const float*)d_in[12],
        (float*)d_out);
}